// round 14
// baseline (speedup 1.0000x reference)
#include <cuda_runtime.h>
#include <cstdint>

#define BB 64
#define TT 512
#define DD 256
#define HH 512
#define NG 32            // groups of 8 CTAs
#define GC 8             // CTAs per group
#define BPG 2            // batches per group

typedef unsigned long long ull;

// Scratch (module-static; no runtime allocs)
__device__ float    g_xproj[(size_t)BB * TT * HH];   // 64 MB
__device__ float    g_z[NG][2][BPG][HH];             // z exchange (ping-pong)
__device__ float2   g_part[NG][2][BPG][GC];          // LN partials
__device__ unsigned g_slots[NG][GC];                 // per-CTA step slots

__device__ __forceinline__ void ffma2(ull& acc, ull a, ull b) {
    asm volatile("fma.rn.f32x2 %0, %1, %2, %0;" : "+l"(acc) : "l"(a), "l"(b));
}
__device__ __forceinline__ ull add2(ull a, ull b) {
    ull r; asm("add.rn.f32x2 %0, %1, %2;" : "=l"(r) : "l"(a), "l"(b)); return r;
}
__device__ __forceinline__ ull pack2(float x, float y) {
    ull r; asm("mov.b64 %0, {%1, %2};" : "=l"(r) : "f"(x), "f"(y)); return r;
}
__device__ __forceinline__ float2 unpack2(ull v) {
    float2 r; asm("mov.b64 {%0, %1}, %2;" : "=f"(r.x), "=f"(r.y) : "l"(v)); return r;
}
__device__ __forceinline__ ull ldcg64(const float* p) {
    ull v; asm volatile("ld.global.cg.b64 %0, [%1];" : "=l"(v) : "l"(p)); return v;
}
__device__ __forceinline__ float4 ldcg128(const float4* p) {
    float4 v;
    asm volatile("ld.global.cg.v4.f32 {%0, %1, %2, %3}, [%4];"
                 : "=f"(v.x), "=f"(v.y), "=f"(v.z), "=f"(v.w) : "l"(p));
    return v;
}
__device__ __forceinline__ void stcg64(float* p, ull v) {
    asm volatile("st.global.cg.b64 [%0], %1;" :: "l"(p), "l"(v) : "memory");
}
__device__ __forceinline__ void stcg_f2(float2* p, float x, float y) {
    asm volatile("st.global.cg.v2.f32 [%0], {%1, %2};" :: "l"(p), "f"(x), "f"(y) : "memory");
}
__device__ __forceinline__ unsigned ld_acq(const unsigned* p) {
    unsigned v;
    asm volatile("ld.acquire.gpu.global.u32 %0, [%1];" : "=r"(v) : "l"(p) : "memory");
    return v;
}
__device__ __forceinline__ void st_rel(unsigned* p, unsigned v) {
    asm volatile("st.release.gpu.global.u32 [%0], %1;" :: "l"(p), "r"(v) : "memory");
}
__device__ __forceinline__ float ftanh(float x) {
    float xc = fminf(fmaxf(x, -9.f), 9.f);
    float e  = __expf(2.f * xc);
    return 1.f - __fdividef(2.f, e + 1.f);
}

// ---------------------------------------------------------------------------
// Kernel 1: xproj = inputs @ Wx + b  (f32x2 FMA). Also resets g_slots.
// ---------------------------------------------------------------------------
__global__ void __launch_bounds__(256) xproj_kernel(
    const float* __restrict__ A, const float* __restrict__ Wx,
    const float* __restrict__ bias) {
    __shared__ float As[16][128];
    __shared__ float Bs[16][64];

    const int tid = threadIdx.x;
    if (blockIdx.x == 0 && blockIdx.y == 0 && tid < NG * GC)
        ((unsigned*)g_slots)[tid] = 0;

    const int bm  = blockIdx.x * 128;
    const int bn  = blockIdx.y * 64;
    const int tx  = tid & 15;
    const int ty  = tid >> 4;

    ull acc[4][4];
#pragma unroll
    for (int p = 0; p < 4; ++p)
#pragma unroll
        for (int j = 0; j < 4; ++j) acc[p][j] = 0ull;

    const int m0 = tid >> 2;
    const int q  = tid & 3;
    const int kb = tid >> 4;
    const int jb = tid & 15;

    for (int kt = 0; kt < 16; ++kt) {
        float4 a0 = __ldg((const float4*)(A + (size_t)(bm + m0) * DD + kt * 16) + q);
        float4 a1 = __ldg((const float4*)(A + (size_t)(bm + m0 + 64) * DD + kt * 16) + q);
        float4 bv = __ldg((const float4*)(Wx + (size_t)(kt * 16 + kb) * HH + bn) + jb);
        __syncthreads();
        As[q * 4 + 0][m0] = a0.x; As[q * 4 + 1][m0] = a0.y;
        As[q * 4 + 2][m0] = a0.z; As[q * 4 + 3][m0] = a0.w;
        As[q * 4 + 0][m0 + 64] = a1.x; As[q * 4 + 1][m0 + 64] = a1.y;
        As[q * 4 + 2][m0 + 64] = a1.z; As[q * 4 + 3][m0 + 64] = a1.w;
        *(float4*)&Bs[kb][jb * 4] = bv;
        __syncthreads();
#pragma unroll
        for (int k = 0; k < 16; ++k) {
            ulonglong2 a01 = *(const ulonglong2*)&As[k][ty * 8];
            ulonglong2 a23 = *(const ulonglong2*)&As[k][ty * 8 + 4];
            float4 bq = *(const float4*)&Bs[k][tx * 4];
            ull b0 = pack2(bq.x, bq.x), b1 = pack2(bq.y, bq.y);
            ull b2 = pack2(bq.z, bq.z), b3 = pack2(bq.w, bq.w);
            ffma2(acc[0][0], a01.x, b0); ffma2(acc[0][1], a01.x, b1);
            ffma2(acc[0][2], a01.x, b2); ffma2(acc[0][3], a01.x, b3);
            ffma2(acc[1][0], a01.y, b0); ffma2(acc[1][1], a01.y, b1);
            ffma2(acc[1][2], a01.y, b2); ffma2(acc[1][3], a01.y, b3);
            ffma2(acc[2][0], a23.x, b0); ffma2(acc[2][1], a23.x, b1);
            ffma2(acc[2][2], a23.x, b2); ffma2(acc[2][3], a23.x, b3);
            ffma2(acc[3][0], a23.y, b0); ffma2(acc[3][1], a23.y, b1);
            ffma2(acc[3][2], a23.y, b2); ffma2(acc[3][3], a23.y, b3);
        }
    }

    float4 bb = __ldg((const float4*)(bias + bn) + tx);
#pragma unroll
    for (int p = 0; p < 4; ++p) {
        float2 c0 = unpack2(acc[p][0]), c1 = unpack2(acc[p][1]);
        float2 c2 = unpack2(acc[p][2]), c3 = unpack2(acc[p][3]);
        float4 ve, vo;
        ve.x = c0.x + bb.x; ve.y = c1.x + bb.y; ve.z = c2.x + bb.z; ve.w = c3.x + bb.w;
        vo.x = c0.y + bb.x; vo.y = c1.y + bb.y; vo.z = c2.y + bb.z; vo.w = c3.y + bb.w;
        int row = bm + ty * 8 + p * 2;
        *(float4*)&g_xproj[(size_t)row * HH + bn + tx * 4]       = ve;
        *(float4*)&g_xproj[(size_t)(row + 1) * HH + bn + tx * 4] = vo;
    }
}

// ---------------------------------------------------------------------------
// Kernel 2: persistent scan (R12 skeleton), 2 CTAs/SM. Deltas vs R12:
//  - per-CTA release-store slots replace the atomic flag counter
//  - ALL warps acquire-spin (lane -> slot, __all_sync); bar2 deleted
// ---------------------------------------------------------------------------
#define F_WS    0        // 16384 floats (8192 ull): weight k-half [w][cp][256 k']
#define F_H2    16384    // 1024 floats: h2[512] float2 {b0,b1}
#define F_WPART 17408    // 32 floats  : wpart[2 b][8 w] float2
#define F_TOT   17440
#define SCAN_SMEM (F_TOT * 4)

__global__ void __launch_bounds__(256, 2) scan_kernel(
    const float* __restrict__ h0, const float* __restrict__ Wh,
    const float* __restrict__ gamma, const float* __restrict__ beta,
    float* __restrict__ out) {
    extern __shared__ float smf[];
    ull*    ws    = (ull*)(smf + F_WS);
    float2* h2s   = (float2*)(smf + F_H2);
    float2* wpart = (float2*)(smf + F_WPART);

    const int tid   = threadIdx.x;
    const int w     = tid >> 5;
    const int l     = tid & 31;
    const int g     = blockIdx.x >> 3;
    const int rank  = blockIdx.x & 7;
    const int jbase = rank * 64;
    const int bbase = g * BPG;

    const int  sel  = l >> 4;          // col-pair-group bit (after L16)
    const int  sel2 = (l >> 3) & 1;    // col-pair bit (after L8)
    const int  sel3 = (l >> 2) & 1;    // batch bit (after L4)
    const bool act  = ((l & 3) == 0);  // 8 writer lanes per warp

    // ---- prologue ----
    ull wreg[32];
#pragma unroll
    for (int i = 0; i < 8; ++i)
#pragma unroll
        for (int cp = 0; cp < 4; ++cp)
            wreg[i * 4 + cp] =
                *(const ull*)&Wh[(size_t)(32 * i + l) * HH + jbase + w * 8 + cp * 2];
#pragma unroll
    for (int i = 0; i < 8; ++i)
#pragma unroll
        for (int cp = 0; cp < 4; ++cp)
            ws[w * 1024 + cp * 256 + 32 * i + l] =
                *(const ull*)&Wh[(size_t)(256 + 32 * i + l) * HH + jbase + w * 8 + cp * 2];

    h2s[2 * tid]     = make_float2(h0[(size_t)(bbase + 0) * HH + 2 * tid],
                                   h0[(size_t)(bbase + 1) * HH + 2 * tid]);
    h2s[2 * tid + 1] = make_float2(h0[(size_t)(bbase + 0) * HH + 2 * tid + 1],
                                   h0[(size_t)(bbase + 1) * HH + 2 * tid + 1]);
    const float gm0 = __ldg(&gamma[2 * tid]),     gm1 = __ldg(&gamma[2 * tid + 1]);
    const float bt0 = __ldg(&beta[2 * tid]),      bt1 = __ldg(&beta[2 * tid + 1]);

    // writer-lane addresses
    const int j0 = jbase + w * 8 + (sel * 2 + sel2) * 2;
    const float* xpb = &g_xproj[((size_t)(bbase + sel3) * TT) * HH + j0];
    float* zdst = &g_z[g][0][sel3][j0];         // buf1 = +BPG*HH floats
    const unsigned* myslot = &g_slots[g][l & 7];
    const bool owner = ((tid >> 5) == rank);    // cols 2tid,2tid+1 in [64r,64r+64)

    __syncthreads();
    ull xp = act ? ldcg64(xpb) : 0ull;          // prefetch t = 0

    for (int t = 0; t < TT; ++t) {
        const int buf = t & 1;
        const unsigned target = (unsigned)(t + 1);

        // ---- phase 1: k over lanes (k = 32i + l) ----
        ull A0 = 0, A1 = 0, A2 = 0, A3 = 0;   // [cp0 b0, cp0 b1, cp1 b0, cp1 b1]
        ull A4 = 0, A5 = 0, A6 = 0, A7 = 0;   // [cp2 b0, cp2 b1, cp3 b0, cp3 b1]
#pragma unroll
        for (int i = 0; i < 16; ++i) {
            float2 hv = h2s[i * 32 + l];       // coalesced LDS.64
            ull hb0 = pack2(hv.x, hv.x);
            ull hb1 = pack2(hv.y, hv.y);
            ull w0, w1, w2, w3;
            if (i < 8) {
                w0 = wreg[i * 4 + 0]; w1 = wreg[i * 4 + 1];
                w2 = wreg[i * 4 + 2]; w3 = wreg[i * 4 + 3];
            } else {
                int o = w * 1024 + 32 * (i - 8) + l;
                w0 = ws[o]; w1 = ws[o + 256]; w2 = ws[o + 512]; w3 = ws[o + 768];
            }
            ffma2(A0, w0, hb0); ffma2(A1, w0, hb1);
            ffma2(A2, w1, hb0); ffma2(A3, w1, hb1);
            ffma2(A4, w2, hb0); ffma2(A5, w2, hb1);
            ffma2(A6, w3, hb0); ffma2(A7, w3, hb1);
        }

        // ---- shuffle tree ----
        ull B0, B1, B2, B3;
        {
            ull k0 = sel ? A4 : A0, g0 = sel ? A0 : A4;
            ull k1 = sel ? A5 : A1, g1 = sel ? A1 : A5;
            ull k2 = sel ? A6 : A2, g2 = sel ? A2 : A6;
            ull k3 = sel ? A7 : A3, g3 = sel ? A3 : A7;
            B0 = add2(k0, __shfl_xor_sync(0xffffffffu, g0, 16));
            B1 = add2(k1, __shfl_xor_sync(0xffffffffu, g1, 16));
            B2 = add2(k2, __shfl_xor_sync(0xffffffffu, g2, 16));
            B3 = add2(k3, __shfl_xor_sync(0xffffffffu, g3, 16));
        }
        ull C0, C1;
        {
            ull k0 = sel2 ? B2 : B0, g0 = sel2 ? B0 : B2;
            ull k1 = sel2 ? B3 : B1, g1 = sel2 ? B1 : B3;
            C0 = add2(k0, __shfl_xor_sync(0xffffffffu, g0, 8));
            C1 = add2(k1, __shfl_xor_sync(0xffffffffu, g1, 8));
        }
        ull D;
        {
            ull k = sel3 ? C1 : C0, gv = sel3 ? C0 : C1;
            D = add2(k, __shfl_xor_sync(0xffffffffu, gv, 4));
        }
        D = add2(D, __shfl_xor_sync(0xffffffffu, D, 2));
        D = add2(D, __shfl_xor_sync(0xffffffffu, D, 1));

        // ---- writers: z publish (L2) + LN partials ----
        float s = 0.f, qs = 0.f;
        if (act) {
            D = add2(D, xp);
            float2 zz = unpack2(D);
            stcg64(zdst + buf * (BPG * HH), D);
            s  = zz.x + zz.y;
            qs = zz.x * zz.x + zz.y * zz.y;
        }
        s  += __shfl_xor_sync(0xffffffffu, s, 16);
        qs += __shfl_xor_sync(0xffffffffu, qs, 16);
        s  += __shfl_xor_sync(0xffffffffu, s, 8);
        qs += __shfl_xor_sync(0xffffffffu, qs, 8);
        if (l == 0 || l == 4)                  // lane0: b0, lane4: b1
            wpart[sel3 * 8 + w] = make_float2(s, qs);

        if (act) xp = (t + 1 < TT) ? ldcg64(xpb + (size_t)(t + 1) * HH) : 0ull;
        __syncthreads();   // bar1: z stores + wpart program-order complete

        // ---- warp 0: CTA partial reduce (warp-uniform), publish slot ----
        if (w == 0) {
            float2 e = wpart[l & 15];          // [b = (l&15)>>3][w = l&7]
            float ss = e.x, qq = e.y;
#pragma unroll
            for (int o = 1; o <= 4; o <<= 1) { // fold 8 warps of same batch
                ss += __shfl_xor_sync(0xffffffffu, ss, o);
                qq += __shfl_xor_sync(0xffffffffu, qq, o);
            }
            if (l == 0 || l == 8)              // lane0: b0, lane8: b1
                stcg_f2(&g_part[g][buf][l >> 3][rank], ss, qq);
            __syncwarp();
            if (l == 0) st_rel(&g_slots[g][rank], target);
        }

        // ---- ALL warps: acquire spin on the 8 per-CTA slots ----
        {
            unsigned v;
            do { v = ld_acq(myslot); }
            while (!__all_sync(0xffffffffu, v >= target));
        }

        // ---- pulls: z (2 cols x 2 b) + stats (redundant per thread, .cg) ----
        ull za = ldcg64(&g_z[g][buf][0][2 * tid]);   // {z(2t,b0), z(2t+1,b0)}
        ull zb = ldcg64(&g_z[g][buf][1][2 * tid]);
        float m0, r0, m1, r1;
        {
            const float4* pp = (const float4*)&g_part[g][buf][0][0];
            float ss = 0.f, qq = 0.f;
#pragma unroll
            for (int c = 0; c < 4; ++c) {
                float4 v = ldcg128(pp + c);   // coherent L2 read
                ss += v.x + v.z; qq += v.y + v.w;
            }
            m0 = ss * (1.0f / 512.0f);
            r0 = rsqrtf(qq * (1.0f / 512.0f) - m0 * m0 + 1e-3f);
            ss = 0.f; qq = 0.f;
#pragma unroll
            for (int c = 4; c < 8; ++c) {
                float4 v = ldcg128(pp + c);
                ss += v.x + v.z; qq += v.y + v.w;
            }
            m1 = ss * (1.0f / 512.0f);
            r1 = rsqrtf(qq * (1.0f / 512.0f) - m1 * m1 + 1e-3f);
        }

        // ---- epilogue: h for cols 2tid, 2tid+1, both batches ----
        float2 zA = unpack2(za), zB = unpack2(zb);
        float h00 = ftanh((zA.x - m0) * r0 * gm0 + bt0);   // col 2t,   b0
        float h01 = ftanh((zB.x - m1) * r1 * gm0 + bt0);   // col 2t,   b1
        float h10 = ftanh((zA.y - m0) * r0 * gm1 + bt1);   // col 2t+1, b0
        float h11 = ftanh((zB.y - m1) * r1 * gm1 + bt1);
        h2s[2 * tid]     = make_float2(h00, h01);
        h2s[2 * tid + 1] = make_float2(h10, h11);

        if (owner) {
            __stcs(&out[((size_t)(bbase + 0) * TT + t) * HH + 2 * tid],     h00);
            __stcs(&out[((size_t)(bbase + 0) * TT + t) * HH + 2 * tid + 1], h10);
            __stcs(&out[((size_t)(bbase + 1) * TT + t) * HH + 2 * tid],     h01);
            __stcs(&out[((size_t)(bbase + 1) * TT + t) * HH + 2 * tid + 1], h11);
        }
        __syncthreads();   // bar2: h2s ready for next phase 1
    }
}

// ---------------------------------------------------------------------------
extern "C" void kernel_launch(void* const* d_in, const int* in_sizes, int n_in,
                              void* d_out, int out_size) {
    const float* inputs = (const float*)d_in[0];  // [64,512,256]
    const float* h0     = (const float*)d_in[1];  // [64,512]
    const float* Wx     = (const float*)d_in[2];  // [256,512]
    const float* Wh     = (const float*)d_in[3];  // [512,512]
    const float* bias   = (const float*)d_in[4];  // [512]
    const float* gamma  = (const float*)d_in[5];  // [512]
    const float* beta   = (const float*)d_in[6];  // [512]
    float* out = (float*)d_out;                   // [64,512,512]

    cudaFuncSetAttribute(scan_kernel,
                         cudaFuncAttributeMaxDynamicSharedMemorySize, SCAN_SMEM);

    dim3 g1(BB * TT / 128, HH / 64);
    xproj_kernel<<<g1, 256>>>(inputs, Wx, bias);   // also resets g_slots
    scan_kernel<<<NG * GC, 256, SCAN_SMEM>>>(h0, Wh, gamma, beta, out);
}

// round 15
// speedup vs baseline: 1.6270x; 1.6270x over previous
#include <cuda_runtime.h>
#include <cstdint>

#define BB 64
#define TT 512
#define DD 256
#define HH 512
#define NG 32            // groups of 8 CTAs
#define GC 8             // CTAs per group
#define BPG 2            // batches per group

typedef unsigned long long ull;

// Scratch (module-static; no runtime allocs)
__device__ float    g_xproj[(size_t)BB * TT * HH];   // 64 MB
__device__ float    g_z[NG][2][BPG][HH];             // z exchange (ping-pong)
__device__ float2   g_part[NG][2][BPG][GC];          // LN partials
__device__ unsigned g_slots[NG][GC];                 // per-CTA step slots

__device__ __forceinline__ void ffma2(ull& acc, ull a, ull b) {
    asm volatile("fma.rn.f32x2 %0, %1, %2, %0;" : "+l"(acc) : "l"(a), "l"(b));
}
__device__ __forceinline__ ull add2(ull a, ull b) {
    ull r; asm("add.rn.f32x2 %0, %1, %2;" : "=l"(r) : "l"(a), "l"(b)); return r;
}
__device__ __forceinline__ ull pack2(float x, float y) {
    ull r; asm("mov.b64 %0, {%1, %2};" : "=l"(r) : "f"(x), "f"(y)); return r;
}
__device__ __forceinline__ float2 unpack2(ull v) {
    float2 r; asm("mov.b64 {%0, %1}, %2;" : "=f"(r.x), "=f"(r.y) : "l"(v)); return r;
}
__device__ __forceinline__ ull ldcg64(const float* p) {
    ull v; asm volatile("ld.global.cg.b64 %0, [%1];" : "=l"(v) : "l"(p)); return v;
}
__device__ __forceinline__ float4 ldcg128(const float4* p) {
    float4 v;
    asm volatile("ld.global.cg.v4.f32 {%0, %1, %2, %3}, [%4];"
                 : "=f"(v.x), "=f"(v.y), "=f"(v.z), "=f"(v.w) : "l"(p));
    return v;
}
__device__ __forceinline__ void stcg64(float* p, ull v) {
    asm volatile("st.global.cg.b64 [%0], %1;" :: "l"(p), "l"(v) : "memory");
}
__device__ __forceinline__ void stcg_f2(float2* p, float x, float y) {
    asm volatile("st.global.cg.v2.f32 [%0], {%1, %2};" :: "l"(p), "f"(x), "f"(y) : "memory");
}
__device__ __forceinline__ unsigned ld_acq(const unsigned* p) {
    unsigned v;
    asm volatile("ld.acquire.gpu.global.u32 %0, [%1];" : "=r"(v) : "l"(p) : "memory");
    return v;
}
__device__ __forceinline__ void st_rel(unsigned* p, unsigned v) {
    asm volatile("st.release.gpu.global.u32 [%0], %1;" :: "l"(p), "r"(v) : "memory");
}
__device__ __forceinline__ float ftanh(float x) {
    float xc = fminf(fmaxf(x, -9.f), 9.f);
    float e  = __expf(2.f * xc);
    return 1.f - __fdividef(2.f, e + 1.f);
}

// ---------------------------------------------------------------------------
// Kernel 1: xproj = inputs @ Wx + b  (f32x2 FMA). Also resets g_slots.
// ---------------------------------------------------------------------------
__global__ void __launch_bounds__(256) xproj_kernel(
    const float* __restrict__ A, const float* __restrict__ Wx,
    const float* __restrict__ bias) {
    __shared__ float As[16][128];
    __shared__ float Bs[16][64];

    const int tid = threadIdx.x;
    if (blockIdx.x == 0 && blockIdx.y == 0 && tid < NG * GC)
        ((unsigned*)g_slots)[tid] = 0;

    const int bm  = blockIdx.x * 128;
    const int bn  = blockIdx.y * 64;
    const int tx  = tid & 15;
    const int ty  = tid >> 4;

    ull acc[4][4];
#pragma unroll
    for (int p = 0; p < 4; ++p)
#pragma unroll
        for (int j = 0; j < 4; ++j) acc[p][j] = 0ull;

    const int m0 = tid >> 2;
    const int q  = tid & 3;
    const int kb = tid >> 4;
    const int jb = tid & 15;

    for (int kt = 0; kt < 16; ++kt) {
        float4 a0 = __ldg((const float4*)(A + (size_t)(bm + m0) * DD + kt * 16) + q);
        float4 a1 = __ldg((const float4*)(A + (size_t)(bm + m0 + 64) * DD + kt * 16) + q);
        float4 bv = __ldg((const float4*)(Wx + (size_t)(kt * 16 + kb) * HH + bn) + jb);
        __syncthreads();
        As[q * 4 + 0][m0] = a0.x; As[q * 4 + 1][m0] = a0.y;
        As[q * 4 + 2][m0] = a0.z; As[q * 4 + 3][m0] = a0.w;
        As[q * 4 + 0][m0 + 64] = a1.x; As[q * 4 + 1][m0 + 64] = a1.y;
        As[q * 4 + 2][m0 + 64] = a1.z; As[q * 4 + 3][m0 + 64] = a1.w;
        *(float4*)&Bs[kb][jb * 4] = bv;
        __syncthreads();
#pragma unroll
        for (int k = 0; k < 16; ++k) {
            ulonglong2 a01 = *(const ulonglong2*)&As[k][ty * 8];
            ulonglong2 a23 = *(const ulonglong2*)&As[k][ty * 8 + 4];
            float4 bq = *(const float4*)&Bs[k][tx * 4];
            ull b0 = pack2(bq.x, bq.x), b1 = pack2(bq.y, bq.y);
            ull b2 = pack2(bq.z, bq.z), b3 = pack2(bq.w, bq.w);
            ffma2(acc[0][0], a01.x, b0); ffma2(acc[0][1], a01.x, b1);
            ffma2(acc[0][2], a01.x, b2); ffma2(acc[0][3], a01.x, b3);
            ffma2(acc[1][0], a01.y, b0); ffma2(acc[1][1], a01.y, b1);
            ffma2(acc[1][2], a01.y, b2); ffma2(acc[1][3], a01.y, b3);
            ffma2(acc[2][0], a23.x, b0); ffma2(acc[2][1], a23.x, b1);
            ffma2(acc[2][2], a23.x, b2); ffma2(acc[2][3], a23.x, b3);
            ffma2(acc[3][0], a23.y, b0); ffma2(acc[3][1], a23.y, b1);
            ffma2(acc[3][2], a23.y, b2); ffma2(acc[3][3], a23.y, b3);
        }
    }

    float4 bb = __ldg((const float4*)(bias + bn) + tx);
#pragma unroll
    for (int p = 0; p < 4; ++p) {
        float2 c0 = unpack2(acc[p][0]), c1 = unpack2(acc[p][1]);
        float2 c2 = unpack2(acc[p][2]), c3 = unpack2(acc[p][3]);
        float4 ve, vo;
        ve.x = c0.x + bb.x; ve.y = c1.x + bb.y; ve.z = c2.x + bb.z; ve.w = c3.x + bb.w;
        vo.x = c0.y + bb.x; vo.y = c1.y + bb.y; vo.z = c2.y + bb.z; vo.w = c3.y + bb.w;
        int row = bm + ty * 8 + p * 2;
        *(float4*)&g_xproj[(size_t)row * HH + bn + tx * 4]       = ve;
        *(float4*)&g_xproj[(size_t)(row + 1) * HH + bn + tx * 4] = vo;
    }
}

// ---------------------------------------------------------------------------
// Kernel 2: persistent scan (R12 skeleton), 2 CTAs/SM. Delta vs R12 ONLY:
// per-CTA release-store slots replace the serializing atomic counter; warp 0
// alone spins (warp-uniform, lane -> slot); other warps parked on bar2.
// ---------------------------------------------------------------------------
#define F_WS    0        // 16384 floats (8192 ull): weight k-half [w][cp][256 k']
#define F_H2    16384    // 1024 floats: h2[512] float2 {b0,b1}
#define F_WPART 17408    // 32 floats  : wpart[2 b][8 w] float2
#define F_TOT   17440
#define SCAN_SMEM (F_TOT * 4)

__global__ void __launch_bounds__(256, 2) scan_kernel(
    const float* __restrict__ h0, const float* __restrict__ Wh,
    const float* __restrict__ gamma, const float* __restrict__ beta,
    float* __restrict__ out) {
    extern __shared__ float smf[];
    ull*    ws    = (ull*)(smf + F_WS);
    float2* h2s   = (float2*)(smf + F_H2);
    float2* wpart = (float2*)(smf + F_WPART);

    const int tid   = threadIdx.x;
    const int w     = tid >> 5;
    const int l     = tid & 31;
    const int g     = blockIdx.x >> 3;
    const int rank  = blockIdx.x & 7;
    const int jbase = rank * 64;
    const int bbase = g * BPG;

    const int  sel  = l >> 4;          // col-pair-group bit (after L16)
    const int  sel2 = (l >> 3) & 1;    // col-pair bit (after L8)
    const int  sel3 = (l >> 2) & 1;    // batch bit (after L4)
    const bool act  = ((l & 3) == 0);  // 8 writer lanes per warp

    // ---- prologue ----
    ull wreg[32];
#pragma unroll
    for (int i = 0; i < 8; ++i)
#pragma unroll
        for (int cp = 0; cp < 4; ++cp)
            wreg[i * 4 + cp] =
                *(const ull*)&Wh[(size_t)(32 * i + l) * HH + jbase + w * 8 + cp * 2];
#pragma unroll
    for (int i = 0; i < 8; ++i)
#pragma unroll
        for (int cp = 0; cp < 4; ++cp)
            ws[w * 1024 + cp * 256 + 32 * i + l] =
                *(const ull*)&Wh[(size_t)(256 + 32 * i + l) * HH + jbase + w * 8 + cp * 2];

    h2s[2 * tid]     = make_float2(h0[(size_t)(bbase + 0) * HH + 2 * tid],
                                   h0[(size_t)(bbase + 1) * HH + 2 * tid]);
    h2s[2 * tid + 1] = make_float2(h0[(size_t)(bbase + 0) * HH + 2 * tid + 1],
                                   h0[(size_t)(bbase + 1) * HH + 2 * tid + 1]);
    const float gm0 = __ldg(&gamma[2 * tid]),     gm1 = __ldg(&gamma[2 * tid + 1]);
    const float bt0 = __ldg(&beta[2 * tid]),      bt1 = __ldg(&beta[2 * tid + 1]);

    // writer-lane addresses
    const int j0 = jbase + w * 8 + (sel * 2 + sel2) * 2;
    const float* xpb = &g_xproj[((size_t)(bbase + sel3) * TT) * HH + j0];
    float* zdst = &g_z[g][0][sel3][j0];         // buf1 = +BPG*HH floats
    const unsigned* myslot = &g_slots[g][l & 7];
    const bool owner = ((tid >> 5) == rank);    // cols 2tid,2tid+1 in [64r,64r+64)

    __syncthreads();
    ull xp = act ? ldcg64(xpb) : 0ull;          // prefetch t = 0

    for (int t = 0; t < TT; ++t) {
        const int buf = t & 1;
        const unsigned target = (unsigned)(t + 1);

        // ---- phase 1: k over lanes (k = 32i + l) ----
        ull A0 = 0, A1 = 0, A2 = 0, A3 = 0;   // [cp0 b0, cp0 b1, cp1 b0, cp1 b1]
        ull A4 = 0, A5 = 0, A6 = 0, A7 = 0;   // [cp2 b0, cp2 b1, cp3 b0, cp3 b1]
#pragma unroll
        for (int i = 0; i < 16; ++i) {
            float2 hv = h2s[i * 32 + l];       // coalesced LDS.64
            ull hb0 = pack2(hv.x, hv.x);
            ull hb1 = pack2(hv.y, hv.y);
            ull w0, w1, w2, w3;
            if (i < 8) {
                w0 = wreg[i * 4 + 0]; w1 = wreg[i * 4 + 1];
                w2 = wreg[i * 4 + 2]; w3 = wreg[i * 4 + 3];
            } else {
                int o = w * 1024 + 32 * (i - 8) + l;
                w0 = ws[o]; w1 = ws[o + 256]; w2 = ws[o + 512]; w3 = ws[o + 768];
            }
            ffma2(A0, w0, hb0); ffma2(A1, w0, hb1);
            ffma2(A2, w1, hb0); ffma2(A3, w1, hb1);
            ffma2(A4, w2, hb0); ffma2(A5, w2, hb1);
            ffma2(A6, w3, hb0); ffma2(A7, w3, hb1);
        }

        // ---- shuffle tree ----
        ull B0, B1, B2, B3;
        {
            ull k0 = sel ? A4 : A0, g0 = sel ? A0 : A4;
            ull k1 = sel ? A5 : A1, g1 = sel ? A1 : A5;
            ull k2 = sel ? A6 : A2, g2 = sel ? A2 : A6;
            ull k3 = sel ? A7 : A3, g3 = sel ? A3 : A7;
            B0 = add2(k0, __shfl_xor_sync(0xffffffffu, g0, 16));
            B1 = add2(k1, __shfl_xor_sync(0xffffffffu, g1, 16));
            B2 = add2(k2, __shfl_xor_sync(0xffffffffu, g2, 16));
            B3 = add2(k3, __shfl_xor_sync(0xffffffffu, g3, 16));
        }
        ull C0, C1;
        {
            ull k0 = sel2 ? B2 : B0, g0 = sel2 ? B0 : B2;
            ull k1 = sel2 ? B3 : B1, g1 = sel2 ? B1 : B3;
            C0 = add2(k0, __shfl_xor_sync(0xffffffffu, g0, 8));
            C1 = add2(k1, __shfl_xor_sync(0xffffffffu, g1, 8));
        }
        ull D;
        {
            ull k = sel3 ? C1 : C0, gv = sel3 ? C0 : C1;
            D = add2(k, __shfl_xor_sync(0xffffffffu, gv, 4));
        }
        D = add2(D, __shfl_xor_sync(0xffffffffu, D, 2));
        D = add2(D, __shfl_xor_sync(0xffffffffu, D, 1));

        // ---- writers: z publish (L2) + LN partials ----
        float s = 0.f, qs = 0.f;
        if (act) {
            D = add2(D, xp);
            float2 zz = unpack2(D);
            stcg64(zdst + buf * (BPG * HH), D);
            s  = zz.x + zz.y;
            qs = zz.x * zz.x + zz.y * zz.y;
        }
        s  += __shfl_xor_sync(0xffffffffu, s, 16);
        qs += __shfl_xor_sync(0xffffffffu, qs, 16);
        s  += __shfl_xor_sync(0xffffffffu, s, 8);
        qs += __shfl_xor_sync(0xffffffffu, qs, 8);
        if (l == 0 || l == 4)                  // lane0: b0, lane4: b1
            wpart[sel3 * 8 + w] = make_float2(s, qs);

        if (act) xp = (t + 1 < TT) ? ldcg64(xpb + (size_t)(t + 1) * HH) : 0ull;
        __syncthreads();   // bar1: z stores + wpart program-order complete

        // ---- warp 0: CTA reduce, publish slot, spin (others park on bar2) ----
        if (w == 0) {
            float2 e = wpart[l & 15];          // [b = (l&15)>>3][w = l&7]
            float ss = e.x, qq = e.y;
#pragma unroll
            for (int o = 1; o <= 4; o <<= 1) { // fold 8 warps of same batch
                ss += __shfl_xor_sync(0xffffffffu, ss, o);
                qq += __shfl_xor_sync(0xffffffffu, qq, o);
            }
            if (l == 0 || l == 8)              // lane0: b0, lane8: b1
                stcg_f2(&g_part[g][buf][l >> 3][rank], ss, qq);
            __syncwarp();
            if (l == 0) st_rel(&g_slots[g][rank], target);
            // warp-uniform spin over the 8 slots (lane -> slot l&7)
            unsigned v;
            do { v = ld_acq(myslot); }
            while (!__all_sync(0xffffffffu, v >= target));
        }
        __syncthreads();   // bar2: all warps ordered after the acquire

        // ---- pulls: z (2 cols x 2 b) + stats (redundant per thread, .cg) ----
        ull za = ldcg64(&g_z[g][buf][0][2 * tid]);   // {z(2t,b0), z(2t+1,b0)}
        ull zb = ldcg64(&g_z[g][buf][1][2 * tid]);
        float m0, r0, m1, r1;
        {
            const float4* pp = (const float4*)&g_part[g][buf][0][0];
            float ss = 0.f, qq = 0.f;
#pragma unroll
            for (int c = 0; c < 4; ++c) {
                float4 v = ldcg128(pp + c);   // coherent L2 read
                ss += v.x + v.z; qq += v.y + v.w;
            }
            m0 = ss * (1.0f / 512.0f);
            r0 = rsqrtf(qq * (1.0f / 512.0f) - m0 * m0 + 1e-3f);
            ss = 0.f; qq = 0.f;
#pragma unroll
            for (int c = 4; c < 8; ++c) {
                float4 v = ldcg128(pp + c);
                ss += v.x + v.z; qq += v.y + v.w;
            }
            m1 = ss * (1.0f / 512.0f);
            r1 = rsqrtf(qq * (1.0f / 512.0f) - m1 * m1 + 1e-3f);
        }

        // ---- epilogue: h for cols 2tid, 2tid+1, both batches ----
        float2 zA = unpack2(za), zB = unpack2(zb);
        float h00 = ftanh((zA.x - m0) * r0 * gm0 + bt0);   // col 2t,   b0
        float h01 = ftanh((zB.x - m1) * r1 * gm0 + bt0);   // col 2t,   b1
        float h10 = ftanh((zA.y - m0) * r0 * gm1 + bt1);   // col 2t+1, b0
        float h11 = ftanh((zB.y - m1) * r1 * gm1 + bt1);
        h2s[2 * tid]     = make_float2(h00, h01);
        h2s[2 * tid + 1] = make_float2(h10, h11);

        if (owner) {
            __stcs(&out[((size_t)(bbase + 0) * TT + t) * HH + 2 * tid],     h00);
            __stcs(&out[((size_t)(bbase + 0) * TT + t) * HH + 2 * tid + 1], h10);
            __stcs(&out[((size_t)(bbase + 1) * TT + t) * HH + 2 * tid],     h01);
            __stcs(&out[((size_t)(bbase + 1) * TT + t) * HH + 2 * tid + 1], h11);
        }
        __syncthreads();   // bar3: h2s ready for next phase 1
    }
}

// ---------------------------------------------------------------------------
extern "C" void kernel_launch(void* const* d_in, const int* in_sizes, int n_in,
                              void* d_out, int out_size) {
    const float* inputs = (const float*)d_in[0];  // [64,512,256]
    const float* h0     = (const float*)d_in[1];  // [64,512]
    const float* Wx     = (const float*)d_in[2];  // [256,512]
    const float* Wh     = (const float*)d_in[3];  // [512,512]
    const float* bias   = (const float*)d_in[4];  // [512]
    const float* gamma  = (const float*)d_in[5];  // [512]
    const float* beta   = (const float*)d_in[6];  // [512]
    float* out = (float*)d_out;                   // [64,512,512]

    cudaFuncSetAttribute(scan_kernel,
                         cudaFuncAttributeMaxDynamicSharedMemorySize, SCAN_SMEM);

    dim3 g1(BB * TT / 128, HH / 64);
    xproj_kernel<<<g1, 256>>>(inputs, Wx, bias);   // also resets g_slots
    scan_kernel<<<NG * GC, 256, SCAN_SMEM>>>(h0, Wh, gamma, beta, out);
}

// round 16
// speedup vs baseline: 4.5370x; 2.7886x over previous
#include <cuda_runtime.h>
#include <cstdint>

#define BB 64
#define TT 512
#define DD 256
#define HH 512
#define NG 32            // groups of 8 CTAs
#define GC 8             // CTAs per group
#define BPG 2            // batches per group

typedef unsigned long long ull;

// Scratch (module-static; no runtime allocs)
__device__ float    g_xproj[(size_t)BB * TT * HH];   // 64 MB
__device__ float    g_z[NG][2][BPG][HH];             // z exchange (ping-pong)
__device__ float2   g_part[NG][2][BPG][GC];          // LN partials
__device__ unsigned g_flag[NG];                      // per-group step counters

__device__ __forceinline__ void ffma2(ull& acc, ull a, ull b) {
    asm volatile("fma.rn.f32x2 %0, %1, %2, %0;" : "+l"(acc) : "l"(a), "l"(b));
}
__device__ __forceinline__ ull add2(ull a, ull b) {
    ull r; asm("add.rn.f32x2 %0, %1, %2;" : "=l"(r) : "l"(a), "l"(b)); return r;
}
__device__ __forceinline__ ull pack2(float x, float y) {
    ull r; asm("mov.b64 %0, {%1, %2};" : "=l"(r) : "f"(x), "f"(y)); return r;
}
__device__ __forceinline__ float2 unpack2(ull v) {
    float2 r; asm("mov.b64 {%0, %1}, %2;" : "=f"(r.x), "=f"(r.y) : "l"(v)); return r;
}
__device__ __forceinline__ ull ldcg64(const float* p) {
    ull v; asm volatile("ld.global.cg.b64 %0, [%1];" : "=l"(v) : "l"(p)); return v;
}
__device__ __forceinline__ float4 ldcg128(const float4* p) {
    float4 v;
    asm volatile("ld.global.cg.v4.f32 {%0, %1, %2, %3}, [%4];"
                 : "=f"(v.x), "=f"(v.y), "=f"(v.z), "=f"(v.w) : "l"(p));
    return v;
}
__device__ __forceinline__ void stcg64(float* p, ull v) {
    asm volatile("st.global.cg.b64 [%0], %1;" :: "l"(p), "l"(v) : "memory");
}
__device__ __forceinline__ void stcg_f2(float2* p, float x, float y) {
    asm volatile("st.global.cg.v2.f32 [%0], {%1, %2};" :: "l"(p), "f"(x), "f"(y) : "memory");
}
__device__ __forceinline__ unsigned ld_acq(const unsigned* p) {
    unsigned v;
    asm volatile("ld.acquire.gpu.global.u32 %0, [%1];" : "=r"(v) : "l"(p) : "memory");
    return v;
}
__device__ __forceinline__ void red_rel_add(unsigned* p, unsigned v) {
    asm volatile("red.release.gpu.global.add.u32 [%0], %1;" :: "l"(p), "r"(v) : "memory");
}
__device__ __forceinline__ float ftanh(float x) {
    float xc = fminf(fmaxf(x, -9.f), 9.f);
    float e  = __expf(2.f * xc);
    return 1.f - __fdividef(2.f, e + 1.f);
}

// ---------------------------------------------------------------------------
// Kernel 1: xproj = inputs @ Wx + b.  BM=128, BN=128, BK=16, 256 threads,
// 8x8 micro-tile in f32x2. Also resets g_flag.
// ---------------------------------------------------------------------------
__global__ void __launch_bounds__(256) xproj_kernel(
    const float* __restrict__ A, const float* __restrict__ Wx,
    const float* __restrict__ bias) {
    __shared__ float As[16][128];
    __shared__ float Bs[16][128];

    const int tid = threadIdx.x;
    if (blockIdx.x == 0 && blockIdx.y == 0 && tid < NG) g_flag[tid] = 0;

    const int bm = blockIdx.x * 128;
    const int bn = blockIdx.y * 128;
    const int tx = tid & 15;    // col group (8 cols)
    const int ty = tid >> 4;    // row group (8 rows = 4 pairs)

    ull acc[4][8];              // [row-pair][col]
#pragma unroll
    for (int p = 0; p < 4; ++p)
#pragma unroll
        for (int j = 0; j < 8; ++j) acc[p][j] = 0ull;

    // A-load indices: r = tid>>1 (0..127), half = tid&1 (k 0-7 / 8-15)
    const int ar   = tid >> 1;
    const int ahalf = tid & 1;
    // B-load indices: kb = tid&15 (k row), c4 = tid>>4 (0..15): cols c4*4, c4*4+64
    const int kb = tid & 15;
    const int c4 = tid >> 4;

    for (int kt = 0; kt < 16; ++kt) {
        float4 a0 = __ldg((const float4*)(A + (size_t)(bm + ar) * DD + kt * 16 + ahalf * 8));
        float4 a1 = __ldg((const float4*)(A + (size_t)(bm + ar) * DD + kt * 16 + ahalf * 8 + 4));
        float4 b0 = __ldg((const float4*)(Wx + (size_t)(kt * 16 + kb) * HH + bn + c4 * 4));
        float4 b1 = __ldg((const float4*)(Wx + (size_t)(kt * 16 + kb) * HH + bn + c4 * 4 + 64));
        __syncthreads();
        As[ahalf * 8 + 0][ar] = a0.x; As[ahalf * 8 + 1][ar] = a0.y;
        As[ahalf * 8 + 2][ar] = a0.z; As[ahalf * 8 + 3][ar] = a0.w;
        As[ahalf * 8 + 4][ar] = a1.x; As[ahalf * 8 + 5][ar] = a1.y;
        As[ahalf * 8 + 6][ar] = a1.z; As[ahalf * 8 + 7][ar] = a1.w;
        *(float4*)&Bs[kb][c4 * 4]      = b0;
        *(float4*)&Bs[kb][c4 * 4 + 64] = b1;
        __syncthreads();
#pragma unroll
        for (int k = 0; k < 16; ++k) {
            ulonglong2 a01 = *(const ulonglong2*)&As[k][ty * 8];      // {r0,r1},{r2,r3}
            ulonglong2 a23 = *(const ulonglong2*)&As[k][ty * 8 + 4];  // {r4,r5},{r6,r7}
            float4 bq0 = *(const float4*)&Bs[k][tx * 8];
            float4 bq1 = *(const float4*)&Bs[k][tx * 8 + 4];
            ull bd[8];
            bd[0] = pack2(bq0.x, bq0.x); bd[1] = pack2(bq0.y, bq0.y);
            bd[2] = pack2(bq0.z, bq0.z); bd[3] = pack2(bq0.w, bq0.w);
            bd[4] = pack2(bq1.x, bq1.x); bd[5] = pack2(bq1.y, bq1.y);
            bd[6] = pack2(bq1.z, bq1.z); bd[7] = pack2(bq1.w, bq1.w);
#pragma unroll
            for (int j = 0; j < 8; ++j) {
                ffma2(acc[0][j], a01.x, bd[j]);
                ffma2(acc[1][j], a01.y, bd[j]);
                ffma2(acc[2][j], a23.x, bd[j]);
                ffma2(acc[3][j], a23.y, bd[j]);
            }
        }
    }

    float4 bb0 = __ldg((const float4*)(bias + bn + tx * 8));
    float4 bb1 = __ldg((const float4*)(bias + bn + tx * 8 + 4));
    const float bv[8] = { bb0.x, bb0.y, bb0.z, bb0.w, bb1.x, bb1.y, bb1.z, bb1.w };
#pragma unroll
    for (int p = 0; p < 4; ++p) {
        float ev[8], ov[8];
#pragma unroll
        for (int j = 0; j < 8; ++j) {
            float2 c = unpack2(acc[p][j]);
            ev[j] = c.x + bv[j];
            ov[j] = c.y + bv[j];
        }
        int row = bm + ty * 8 + p * 2;
        float* d0 = &g_xproj[(size_t)row * HH + bn + tx * 8];
        float* d1 = d0 + HH;
        *(float4*)d0       = make_float4(ev[0], ev[1], ev[2], ev[3]);
        *(float4*)(d0 + 4) = make_float4(ev[4], ev[5], ev[6], ev[7]);
        *(float4*)d1       = make_float4(ov[0], ov[1], ov[2], ov[3]);
        *(float4*)(d1 + 4) = make_float4(ov[4], ov[5], ov[6], ov[7]);
    }
}

// ---------------------------------------------------------------------------
// Kernel 2: persistent scan — R12 VERBATIM (proven 1733 us config).
// 2 CTAs/SM; group of 8 CTAs owns 2 batches; weights half regs / half SMEM;
// exchange via L2 (.cg); sync via single atomic counter, warp-0 spin only.
// ---------------------------------------------------------------------------
#define F_WS    0        // 16384 floats (8192 ull): weight k-half [w][cp][256 k']
#define F_H2    16384    // 1024 floats: h2[512] float2 {b0,b1}
#define F_WPART 17408    // 32 floats  : wpart[2 b][8 w] float2
#define F_TOT   17440
#define SCAN_SMEM (F_TOT * 4)

__global__ void __launch_bounds__(256, 2) scan_kernel(
    const float* __restrict__ h0, const float* __restrict__ Wh,
    const float* __restrict__ gamma, const float* __restrict__ beta,
    float* __restrict__ out) {
    extern __shared__ float smf[];
    ull*    ws    = (ull*)(smf + F_WS);
    float2* h2s   = (float2*)(smf + F_H2);
    float2* wpart = (float2*)(smf + F_WPART);

    const int tid   = threadIdx.x;
    const int w     = tid >> 5;
    const int l     = tid & 31;
    const int g     = blockIdx.x >> 3;
    const int rank  = blockIdx.x & 7;
    const int jbase = rank * 64;
    const int bbase = g * BPG;

    const int  sel  = l >> 4;          // col-pair-group bit (after L16)
    const int  sel2 = (l >> 3) & 1;    // col-pair bit (after L8)
    const int  sel3 = (l >> 2) & 1;    // batch bit (after L4)
    const bool act  = ((l & 3) == 0);  // 8 writer lanes per warp

    // ---- prologue ----
    ull wreg[32];
#pragma unroll
    for (int i = 0; i < 8; ++i)
#pragma unroll
        for (int cp = 0; cp < 4; ++cp)
            wreg[i * 4 + cp] =
                *(const ull*)&Wh[(size_t)(32 * i + l) * HH + jbase + w * 8 + cp * 2];
#pragma unroll
    for (int i = 0; i < 8; ++i)
#pragma unroll
        for (int cp = 0; cp < 4; ++cp)
            ws[w * 1024 + cp * 256 + 32 * i + l] =
                *(const ull*)&Wh[(size_t)(256 + 32 * i + l) * HH + jbase + w * 8 + cp * 2];

    h2s[2 * tid]     = make_float2(h0[(size_t)(bbase + 0) * HH + 2 * tid],
                                   h0[(size_t)(bbase + 1) * HH + 2 * tid]);
    h2s[2 * tid + 1] = make_float2(h0[(size_t)(bbase + 0) * HH + 2 * tid + 1],
                                   h0[(size_t)(bbase + 1) * HH + 2 * tid + 1]);
    const float gm0 = __ldg(&gamma[2 * tid]),     gm1 = __ldg(&gamma[2 * tid + 1]);
    const float bt0 = __ldg(&beta[2 * tid]),      bt1 = __ldg(&beta[2 * tid + 1]);

    // writer-lane addresses
    const int j0 = jbase + w * 8 + (sel * 2 + sel2) * 2;
    const float* xpb = &g_xproj[((size_t)(bbase + sel3) * TT) * HH + j0];
    float* zdst = &g_z[g][0][sel3][j0];         // buf1 = +BPG*HH floats
    unsigned* flag = &g_flag[g];
    const bool owner = ((tid >> 5) == rank);    // cols 2tid,2tid+1 in [64r,64r+64)

    __syncthreads();
    ull xp = act ? ldcg64(xpb) : 0ull;          // prefetch t = 0

    for (int t = 0; t < TT; ++t) {
        const int buf = t & 1;

        // ---- phase 1: k over lanes (k = 32i + l) ----
        ull A0 = 0, A1 = 0, A2 = 0, A3 = 0;   // [cp0 b0, cp0 b1, cp1 b0, cp1 b1]
        ull A4 = 0, A5 = 0, A6 = 0, A7 = 0;   // [cp2 b0, cp2 b1, cp3 b0, cp3 b1]
#pragma unroll
        for (int i = 0; i < 16; ++i) {
            float2 hv = h2s[i * 32 + l];       // coalesced LDS.64
            ull hb0 = pack2(hv.x, hv.x);
            ull hb1 = pack2(hv.y, hv.y);
            ull w0, w1, w2, w3;
            if (i < 8) {
                w0 = wreg[i * 4 + 0]; w1 = wreg[i * 4 + 1];
                w2 = wreg[i * 4 + 2]; w3 = wreg[i * 4 + 3];
            } else {
                int o = w * 1024 + 32 * (i - 8) + l;
                w0 = ws[o]; w1 = ws[o + 256]; w2 = ws[o + 512]; w3 = ws[o + 768];
            }
            ffma2(A0, w0, hb0); ffma2(A1, w0, hb1);
            ffma2(A2, w1, hb0); ffma2(A3, w1, hb1);
            ffma2(A4, w2, hb0); ffma2(A5, w2, hb1);
            ffma2(A6, w3, hb0); ffma2(A7, w3, hb1);
        }

        // ---- shuffle tree ----
        ull B0, B1, B2, B3;
        {
            ull k0 = sel ? A4 : A0, g0 = sel ? A0 : A4;
            ull k1 = sel ? A5 : A1, g1 = sel ? A1 : A5;
            ull k2 = sel ? A6 : A2, g2 = sel ? A2 : A6;
            ull k3 = sel ? A7 : A3, g3 = sel ? A3 : A7;
            B0 = add2(k0, __shfl_xor_sync(0xffffffffu, g0, 16));
            B1 = add2(k1, __shfl_xor_sync(0xffffffffu, g1, 16));
            B2 = add2(k2, __shfl_xor_sync(0xffffffffu, g2, 16));
            B3 = add2(k3, __shfl_xor_sync(0xffffffffu, g3, 16));
        }
        ull C0, C1;
        {
            ull k0 = sel2 ? B2 : B0, g0 = sel2 ? B0 : B2;
            ull k1 = sel2 ? B3 : B1, g1 = sel2 ? B1 : B3;
            C0 = add2(k0, __shfl_xor_sync(0xffffffffu, g0, 8));
            C1 = add2(k1, __shfl_xor_sync(0xffffffffu, g1, 8));
        }
        ull D;
        {
            ull k = sel3 ? C1 : C0, gv = sel3 ? C0 : C1;
            D = add2(k, __shfl_xor_sync(0xffffffffu, gv, 4));
        }
        D = add2(D, __shfl_xor_sync(0xffffffffu, D, 2));
        D = add2(D, __shfl_xor_sync(0xffffffffu, D, 1));

        // ---- writers: z publish (L2) + LN partials ----
        float s = 0.f, qs = 0.f;
        if (act) {
            D = add2(D, xp);
            float2 zz = unpack2(D);
            stcg64(zdst + buf * (BPG * HH), D);
            s  = zz.x + zz.y;
            qs = zz.x * zz.x + zz.y * zz.y;
        }
        s  += __shfl_xor_sync(0xffffffffu, s, 16);
        qs += __shfl_xor_sync(0xffffffffu, qs, 16);
        s  += __shfl_xor_sync(0xffffffffu, s, 8);
        qs += __shfl_xor_sync(0xffffffffu, qs, 8);
        if (l == 0 || l == 4)                  // lane0: b0, lane4: b1
            wpart[sel3 * 8 + w] = make_float2(s, qs);

        if (act) xp = (t + 1 < TT) ? ldcg64(xpb + (size_t)(t + 1) * HH) : 0ull;
        __syncthreads();   // bar1: z stores + wpart program-order complete

        // ---- warp 0: CTA partial reduce + publish + arrive + spin ----
        if (w == 0) {
            float2 e = wpart[l & 15];          // [b = (l&15)>>3][w = l&7]
            float ss = e.x, qq = e.y;
#pragma unroll
            for (int o = 1; o <= 4; o <<= 1) { // fold 8 warps of same batch
                ss += __shfl_xor_sync(0xffffffffu, ss, o);
                qq += __shfl_xor_sync(0xffffffffu, qq, o);
            }
            if (l == 0 || l == 8)              // lane0: b0, lane8: b1
                stcg_f2(&g_part[g][buf][l >> 3][rank], ss, qq);
            __syncwarp();
            if (l == 0) red_rel_add(flag, 1u);
            const unsigned target = 8u * (unsigned)(t + 1);
            unsigned v;
            do { v = ld_acq(flag); } while (v < target);
        }
        __syncthreads();   // bar2: whole CTA ordered after all 8 releases

        // ---- pulls: z (2 cols x 2 b) + stats (redundant per thread, .cg) ----
        ull za = ldcg64(&g_z[g][buf][0][2 * tid]);   // {z(2t,b0), z(2t+1,b0)}
        ull zb = ldcg64(&g_z[g][buf][1][2 * tid]);
        float m0, r0, m1, r1;
        {
            const float4* pp = (const float4*)&g_part[g][buf][0][0];
            float ss = 0.f, qq = 0.f;
#pragma unroll
            for (int c = 0; c < 4; ++c) {
                float4 v = ldcg128(pp + c);   // coherent L2 read
                ss += v.x + v.z; qq += v.y + v.w;
            }
            m0 = ss * (1.0f / 512.0f);
            r0 = rsqrtf(qq * (1.0f / 512.0f) - m0 * m0 + 1e-3f);
            ss = 0.f; qq = 0.f;
#pragma unroll
            for (int c = 4; c < 8; ++c) {
                float4 v = ldcg128(pp + c);
                ss += v.x + v.z; qq += v.y + v.w;
            }
            m1 = ss * (1.0f / 512.0f);
            r1 = rsqrtf(qq * (1.0f / 512.0f) - m1 * m1 + 1e-3f);
        }

        // ---- epilogue: h for cols 2tid, 2tid+1, both batches ----
        float2 zA = unpack2(za), zB = unpack2(zb);
        float h00 = ftanh((zA.x - m0) * r0 * gm0 + bt0);   // col 2t,   b0
        float h01 = ftanh((zB.x - m1) * r1 * gm0 + bt0);   // col 2t,   b1
        float h10 = ftanh((zA.y - m0) * r0 * gm1 + bt1);   // col 2t+1, b0
        float h11 = ftanh((zB.y - m1) * r1 * gm1 + bt1);
        h2s[2 * tid]     = make_float2(h00, h01);
        h2s[2 * tid + 1] = make_float2(h10, h11);

        if (owner) {
            __stcs(&out[((size_t)(bbase + 0) * TT + t) * HH + 2 * tid],     h00);
            __stcs(&out[((size_t)(bbase + 0) * TT + t) * HH + 2 * tid + 1], h10);
            __stcs(&out[((size_t)(bbase + 1) * TT + t) * HH + 2 * tid],     h01);
            __stcs(&out[((size_t)(bbase + 1) * TT + t) * HH + 2 * tid + 1], h11);
        }
        __syncthreads();   // bar3: h2s ready for next phase 1
    }
}

// ---------------------------------------------------------------------------
extern "C" void kernel_launch(void* const* d_in, const int* in_sizes, int n_in,
                              void* d_out, int out_size) {
    const float* inputs = (const float*)d_in[0];  // [64,512,256]
    const float* h0     = (const float*)d_in[1];  // [64,512]
    const float* Wx     = (const float*)d_in[2];  // [256,512]
    const float* Wh     = (const float*)d_in[3];  // [512,512]
    const float* bias   = (const float*)d_in[4];  // [512]
    const float* gamma  = (const float*)d_in[5];  // [512]
    const float* beta   = (const float*)d_in[6];  // [512]
    float* out = (float*)d_out;                   // [64,512,512]

    cudaFuncSetAttribute(scan_kernel,
                         cudaFuncAttributeMaxDynamicSharedMemorySize, SCAN_SMEM);

    dim3 g1(BB * TT / 128, HH / 128);
    xproj_kernel<<<g1, 256>>>(inputs, Wx, bias);   // also resets g_flag
    scan_kernel<<<NG * GC, 256, SCAN_SMEM>>>(h0, Wh, gamma, beta, out);
}